// round 8
// baseline (speedup 1.0000x reference)
#include <cuda_runtime.h>
#include <cuda_bf16.h>
#include <cstdint>

#define NB 128
#define NR 1152
#define NC 32
#define NI 64
#define NCO 1024
#define RPC 32
#define RCH 36

__device__ float g_uhat[(size_t)NB * NR * NCO];    // [b][r][co] ~604 MB
__device__ float g_spart[(size_t)RCH * NB * NCO];  // [ch][b][co]
__device__ float g_vacc[(size_t)NB * NCO];

// ---------------------------------------------------------------------------
// K1: u_hat GEMM via warp-level bf16 mma.sync with 3-term hi/lo split.
// grid (16 co-chunks, 1152 r). CTA tile: M=128(b) x N=64(co) x K=64(i).
// 8 warps: 4 in M x 2 in N; warp tile 32x32 -> 2 m-tiles x 4 n-tiles m16n8k16.
// smem bf16 hi/lo, rows 128B, 16B-chunk XOR swizzle (c ^ (row&7)).
// ---------------------------------------------------------------------------
__device__ __forceinline__ unsigned su32(const void* p) {
    unsigned a;
    asm("{ .reg .u64 t; cvta.to.shared.u64 t,%1; cvt.u32.u64 %0,t; }" : "=r"(a) : "l"(p));
    return a;
}
__device__ __forceinline__ void ldm4(unsigned* r, unsigned a) {
    asm volatile("ldmatrix.sync.aligned.m8n8.x4.shared.b16 {%0,%1,%2,%3}, [%4];"
                 : "=r"(r[0]), "=r"(r[1]), "=r"(r[2]), "=r"(r[3]) : "r"(a));
}
__device__ __forceinline__ void mma16816(float* d, const unsigned* a, const unsigned* b) {
    asm volatile(
        "mma.sync.aligned.m16n8k16.row.col.f32.bf16.bf16.f32 "
        "{%0,%1,%2,%3}, {%4,%5,%6,%7}, {%8,%9}, {%0,%1,%2,%3};"
        : "+f"(d[0]), "+f"(d[1]), "+f"(d[2]), "+f"(d[3])
        : "r"(a[0]), "r"(a[1]), "r"(a[2]), "r"(a[3]), "r"(b[0]), "r"(b[1]));
}

__global__ void __launch_bounds__(256)
k_uhat(const float* __restrict__ x, const float* __restrict__ W) {
    __shared__ __align__(16) __nv_bfloat16 xh[NB * NI], xl[NB * NI];  // 16KB each
    __shared__ __align__(16) __nv_bfloat16 wh[64 * NI], wl[64 * NI];  //  8KB each
    const int cobase = blockIdx.x * 64;
    const int r = blockIdx.y;
    const int tid = threadIdx.x, wid = tid >> 5, lane = tid & 31;

    // ---- load + split-convert. task = (row, 16B-chunk c): 8 fp32 -> hi/lo chunks
    auto put = [](__nv_bfloat16* hi, __nv_bfloat16* lo, int row, int c,
                  const float4 f0, const float4 f1) {
        unsigned o = (row * 8 + (c ^ (row & 7))) * 8;  // bf16 elements
        float a[8] = {f0.x, f0.y, f0.z, f0.w, f1.x, f1.y, f1.z, f1.w};
        unsigned hv[4], lv[4];
#pragma unroll
        for (int j = 0; j < 4; j++) {
            __nv_bfloat162 h = __floats2bfloat162_rn(a[2 * j], a[2 * j + 1]);
            float r0 = a[2 * j] - __bfloat162float(h.x);
            float r1 = a[2 * j + 1] - __bfloat162float(h.y);
            __nv_bfloat162 l = __floats2bfloat162_rn(r0, r1);
            hv[j] = *(unsigned*)&h;
            lv[j] = *(unsigned*)&l;
        }
        *(uint4*)&hi[o] = make_uint4(hv[0], hv[1], hv[2], hv[3]);
        *(uint4*)&lo[o] = make_uint4(lv[0], lv[1], lv[2], lv[3]);
    };
    // x: 128 rows x 8 chunks = 1024 tasks
    for (int i = tid; i < 1024; i += 256) {
        int row = i >> 3, c = i & 7;
        const float* p = x + ((size_t)row * NR + r) * NI + c * 8;
        put(xh, xl, row, c, *(const float4*)p, *(const float4*)(p + 4));
    }
    // W: 64 rows x 8 chunks = 512 tasks
    for (int i = tid; i < 512; i += 256) {
        int row = i >> 3, c = i & 7;
        const float* p = W + ((size_t)r * NCO + cobase + row) * NI + c * 8;
        put(wh, wl, row, c, *(const float4*)p, *(const float4*)(p + 4));
    }
    __syncthreads();

    // ---- fragment address helpers (per-lane constants)
    const int warpM = wid >> 1, warpN = wid & 1;       // 4 x 2
    const int lrow = (lane & 7) + ((lane >> 3) & 1) * 8;
    const unsigned csel = lane >> 4;
    // A tile row bases (bf16 elem index), mt in {0,1}
    unsigned arow[2], brow[2];
#pragma unroll
    for (int mt = 0; mt < 2; mt++) arow[mt] = (warpM * 32 + mt * 16 + lrow);
#pragma unroll
    for (int np = 0; np < 2; np++) brow[np] = (warpN * 32 + np * 16 + lrow);

    float acc[2][4][4];
#pragma unroll
    for (int mt = 0; mt < 2; mt++)
#pragma unroll
        for (int nt = 0; nt < 4; nt++)
#pragma unroll
            for (int j = 0; j < 4; j++) acc[mt][nt][j] = 0.f;

    const unsigned bxh = su32(xh), bxl = su32(xl);
    const unsigned bwh = su32(wh), bwl = su32(wl);

#pragma unroll
    for (int kk = 0; kk < 4; kk++) {
        unsigned Ah[2][4], Al[2][4], Bh[2][4], Bl[2][4];
#pragma unroll
        for (int mt = 0; mt < 2; mt++) {
            unsigned rs = arow[mt] & 7;
            unsigned off = arow[mt] * 128u + (((2u * kk + csel) ^ rs) << 4);
            ldm4(Ah[mt], bxh + off);
            ldm4(Al[mt], bxl + off);
        }
#pragma unroll
        for (int np = 0; np < 2; np++) {
            unsigned rs = brow[np] & 7;
            unsigned off = brow[np] * 128u + (((2u * kk + csel) ^ rs) << 4);
            ldm4(Bh[np], bwh + off);
            ldm4(Bl[np], bwl + off);
        }
#pragma unroll
        for (int mt = 0; mt < 2; mt++)
#pragma unroll
            for (int np = 0; np < 2; np++)
#pragma unroll
                for (int sub = 0; sub < 2; sub++) {
                    unsigned bh[2] = {Bh[np][sub], Bh[np][sub + 2]};
                    unsigned bl[2] = {Bl[np][sub], Bl[np][sub + 2]};
                    float* d = acc[mt][np * 2 + sub];
                    mma16816(d, Ah[mt], bh);
                    mma16816(d, Ah[mt], bl);
                    mma16816(d, Al[mt], bh);
                }
    }

    // ---- epilogue: direct STG.64, 32B segments per lane-quad
    const int er0 = lane >> 2, ec = (lane & 3) * 2;
#pragma unroll
    for (int mt = 0; mt < 2; mt++)
#pragma unroll
        for (int nt = 0; nt < 4; nt++) {
            int b0 = warpM * 32 + mt * 16 + er0;
            int co = cobase + warpN * 32 + nt * 8 + ec;
            float* p0 = &g_uhat[((size_t)b0 * NR + r) * NCO + co];
            float* p1 = &g_uhat[((size_t)(b0 + 8) * NR + r) * NCO + co];
            *(float2*)p0 = make_float2(acc[mt][nt][0], acc[mt][nt][1]);
            *(float2*)p1 = make_float2(acc[mt][nt][2], acc[mt][nt][3]);
        }
}

// ---------------------------------------------------------------------------
// K2: routing pass, barrier-free hot loop. grid (B, RCH), 256 threads.
// lane = c; lane reads contiguous u[b,r,c,0:32] (128B). Softmax via shfl.
// first=1 -> uniform weights 1/32 (softmax of zero logits).
// ---------------------------------------------------------------------------
__global__ void __launch_bounds__(256)
k_route(int first) {
    const int b = blockIdx.x, ch = blockIdx.y;
    const int tid = threadIdx.x, wid = tid >> 5, lane = tid & 31;
    __shared__ float s_sh[NCO];
    for (int i = tid; i < NCO; i += 256) s_sh[i] = 0.f;

    float4 vv[8];
    if (!first) {
        const float4* vp = (const float4*)&g_vacc[(size_t)b * NCO + lane * 32];
#pragma unroll
        for (int j = 0; j < 8; j++) vv[j] = vp[j];
    }

    float acc[32];
#pragma unroll
    for (int j = 0; j < 32; j++) acc[j] = 0.f;

    for (int rr = wid * 4; rr < wid * 4 + 4; rr++) {
        const int r = ch * RPC + rr;
        const float4* up = (const float4*)&g_uhat[((size_t)b * NR + r) * NCO + lane * 32];
        float4 u[8];
#pragma unroll
        for (int j = 0; j < 8; j++) u[j] = up[j];
        float wgt;
        if (first) {
            wgt = 1.0f / 32.0f;
        } else {
            float p = 0.f;
#pragma unroll
            for (int j = 0; j < 8; j++)
                p += u[j].x * vv[j].x + u[j].y * vv[j].y +
                     u[j].z * vv[j].z + u[j].w * vv[j].w;
            float mx = p;
#pragma unroll
            for (int s = 16; s; s >>= 1)
                mx = fmaxf(mx, __shfl_xor_sync(0xffffffffu, mx, s));
            float e = __expf(p - mx), sum = e;
#pragma unroll
            for (int s = 16; s; s >>= 1)
                sum += __shfl_xor_sync(0xffffffffu, sum, s);
            wgt = e / sum;
        }
#pragma unroll
        for (int j = 0; j < 8; j++) {
            acc[j * 4 + 0] = fmaf(wgt, u[j].x, acc[j * 4 + 0]);
            acc[j * 4 + 1] = fmaf(wgt, u[j].y, acc[j * 4 + 1]);
            acc[j * 4 + 2] = fmaf(wgt, u[j].z, acc[j * 4 + 2]);
            acc[j * 4 + 3] = fmaf(wgt, u[j].w, acc[j * 4 + 3]);
        }
    }
    __syncthreads();
#pragma unroll
    for (int j = 0; j < 32; j++) atomicAdd(&s_sh[lane * 32 + j], acc[j]);
    __syncthreads();
    ((float4*)&g_spart[((size_t)ch * NB + b) * NCO])[tid] = ((float4*)s_sh)[tid];
}

// ---------------------------------------------------------------------------
// K3: reduce over chunks, squash per (b,c), update Vacc / write out.
// ---------------------------------------------------------------------------
__global__ void __launch_bounds__(256)
k_squash(float* __restrict__ out, int iter) {
    const int b = blockIdx.x, t = threadIdx.x;
    float4 s = make_float4(0.f, 0.f, 0.f, 0.f);
    const float4* sp = (const float4*)g_spart + (size_t)b * (NCO / 4) + t;
#pragma unroll 4
    for (int ch = 0; ch < RCH; ch++) {
        float4 p = sp[(size_t)ch * NB * (NCO / 4)];
        s.x += p.x; s.y += p.y; s.z += p.z; s.w += p.w;
    }
    float ss = s.x * s.x + s.y * s.y + s.z * s.z + s.w * s.w;
    ss += __shfl_xor_sync(0xffffffffu, ss, 1);
    ss += __shfl_xor_sync(0xffffffffu, ss, 2);
    ss += __shfl_xor_sync(0xffffffffu, ss, 4);
    float norm = sqrtf(ss);
    float scale = ss / (1.0f + ss) / (norm + 1e-8f);
    float4 v = make_float4(s.x * scale, s.y * scale, s.z * scale, s.w * scale);
    float4* va = (float4*)g_vacc + b * (NCO / 4) + t;
    if (iter == 2) ((float4*)out)[b * (NCO / 4) + t] = v;
    else if (iter == 0) *va = v;
    else { float4 a = *va; a.x += v.x; a.y += v.y; a.z += v.z; a.w += v.w; *va = a; }
}

extern "C" void kernel_launch(void* const* d_in, const int* in_sizes, int n_in,
                              void* d_out, int out_size) {
    const float* x = (const float*)d_in[0];  // [B,R,I]
    const float* W = (const float*)d_in[1];  // [R,C,O,I]
    float* out = (float*)d_out;              // [B,C,O]
    k_uhat<<<dim3(16, NR), 256>>>(x, W);
    k_route<<<dim3(NB, RCH), 256>>>(1);
    k_squash<<<NB, 256>>>(out, 0);
    k_route<<<dim3(NB, RCH), 256>>>(0);
    k_squash<<<NB, 256>>>(out, 1);
    k_route<<<dim3(NB, RCH), 256>>>(0);
    k_squash<<<NB, 256>>>(out, 2);
}

// round 9
// speedup vs baseline: 3.1510x; 3.1510x over previous
#include <cuda_runtime.h>
#include <cuda_bf16.h>
#include <cstdint>

#define NB 128
#define NR 1152
#define NC 32
#define NI 64
#define NCO 1024
#define RPC 32
#define RCH 36

__device__ float g_uhat[(size_t)NB * NR * NCO];    // [b][r][co] ~604 MB
__device__ float g_spart[(size_t)RCH * NB * NCO];  // [ch][b][co]
__device__ float g_vacc[(size_t)NB * NCO];

// ---------------------------------------------------------------------------
// K1: u_hat GEMM via warp-level bf16 mma.sync with 3-term hi/lo split.
// grid (16 co-chunks, 1152 r). CTA tile: M=128(b) x N=64(co) x K=64(i).
// (unchanged from R8: measured ~320us by subtraction, rel_err 4.6e-6)
// ---------------------------------------------------------------------------
__device__ __forceinline__ unsigned su32(const void* p) {
    unsigned a;
    asm("{ .reg .u64 t; cvta.to.shared.u64 t,%1; cvt.u32.u64 %0,t; }" : "=r"(a) : "l"(p));
    return a;
}
__device__ __forceinline__ void ldm4(unsigned* r, unsigned a) {
    asm volatile("ldmatrix.sync.aligned.m8n8.x4.shared.b16 {%0,%1,%2,%3}, [%4];"
                 : "=r"(r[0]), "=r"(r[1]), "=r"(r[2]), "=r"(r[3]) : "r"(a));
}
__device__ __forceinline__ void mma16816(float* d, const unsigned* a, const unsigned* b) {
    asm volatile(
        "mma.sync.aligned.m16n8k16.row.col.f32.bf16.bf16.f32 "
        "{%0,%1,%2,%3}, {%4,%5,%6,%7}, {%8,%9}, {%0,%1,%2,%3};"
        : "+f"(d[0]), "+f"(d[1]), "+f"(d[2]), "+f"(d[3])
        : "r"(a[0]), "r"(a[1]), "r"(a[2]), "r"(a[3]), "r"(b[0]), "r"(b[1]));
}

__global__ void __launch_bounds__(256)
k_uhat(const float* __restrict__ x, const float* __restrict__ W) {
    __shared__ __align__(16) __nv_bfloat16 xh[NB * NI], xl[NB * NI];
    __shared__ __align__(16) __nv_bfloat16 wh[64 * NI], wl[64 * NI];
    const int cobase = blockIdx.x * 64;
    const int r = blockIdx.y;
    const int tid = threadIdx.x, wid = tid >> 5, lane = tid & 31;

    auto put = [](__nv_bfloat16* hi, __nv_bfloat16* lo, int row, int c,
                  const float4 f0, const float4 f1) {
        unsigned o = (row * 8 + (c ^ (row & 7))) * 8;
        float a[8] = {f0.x, f0.y, f0.z, f0.w, f1.x, f1.y, f1.z, f1.w};
        unsigned hv[4], lv[4];
#pragma unroll
        for (int j = 0; j < 4; j++) {
            __nv_bfloat162 h = __floats2bfloat162_rn(a[2 * j], a[2 * j + 1]);
            float r0 = a[2 * j] - __bfloat162float(h.x);
            float r1 = a[2 * j + 1] - __bfloat162float(h.y);
            __nv_bfloat162 l = __floats2bfloat162_rn(r0, r1);
            hv[j] = *(unsigned*)&h;
            lv[j] = *(unsigned*)&l;
        }
        *(uint4*)&hi[o] = make_uint4(hv[0], hv[1], hv[2], hv[3]);
        *(uint4*)&lo[o] = make_uint4(lv[0], lv[1], lv[2], lv[3]);
    };
    for (int i = tid; i < 1024; i += 256) {
        int row = i >> 3, c = i & 7;
        const float* p = x + ((size_t)row * NR + r) * NI + c * 8;
        put(xh, xl, row, c, *(const float4*)p, *(const float4*)(p + 4));
    }
    for (int i = tid; i < 512; i += 256) {
        int row = i >> 3, c = i & 7;
        const float* p = W + ((size_t)r * NCO + cobase + row) * NI + c * 8;
        put(wh, wl, row, c, *(const float4*)p, *(const float4*)(p + 4));
    }
    __syncthreads();

    const int warpM = wid >> 1, warpN = wid & 1;
    const int lrow = (lane & 7) + ((lane >> 3) & 1) * 8;
    const unsigned csel = lane >> 4;
    unsigned arow[2], brow[2];
#pragma unroll
    for (int mt = 0; mt < 2; mt++) arow[mt] = (warpM * 32 + mt * 16 + lrow);
#pragma unroll
    for (int np = 0; np < 2; np++) brow[np] = (warpN * 32 + np * 16 + lrow);

    float acc[2][4][4];
#pragma unroll
    for (int mt = 0; mt < 2; mt++)
#pragma unroll
        for (int nt = 0; nt < 4; nt++)
#pragma unroll
            for (int j = 0; j < 4; j++) acc[mt][nt][j] = 0.f;

    const unsigned bxh = su32(xh), bxl = su32(xl);
    const unsigned bwh = su32(wh), bwl = su32(wl);

#pragma unroll
    for (int kk = 0; kk < 4; kk++) {
        unsigned Ah[2][4], Al[2][4], Bh[2][4], Bl[2][4];
#pragma unroll
        for (int mt = 0; mt < 2; mt++) {
            unsigned rs = arow[mt] & 7;
            unsigned off = arow[mt] * 128u + (((2u * kk + csel) ^ rs) << 4);
            ldm4(Ah[mt], bxh + off);
            ldm4(Al[mt], bxl + off);
        }
#pragma unroll
        for (int np = 0; np < 2; np++) {
            unsigned rs = brow[np] & 7;
            unsigned off = brow[np] * 128u + (((2u * kk + csel) ^ rs) << 4);
            ldm4(Bh[np], bwh + off);
            ldm4(Bl[np], bwl + off);
        }
#pragma unroll
        for (int mt = 0; mt < 2; mt++)
#pragma unroll
            for (int np = 0; np < 2; np++)
#pragma unroll
                for (int sub = 0; sub < 2; sub++) {
                    unsigned bh[2] = {Bh[np][sub], Bh[np][sub + 2]};
                    unsigned bl[2] = {Bl[np][sub], Bl[np][sub + 2]};
                    float* d = acc[mt][np * 2 + sub];
                    mma16816(d, Ah[mt], bh);
                    mma16816(d, Ah[mt], bl);
                    mma16816(d, Al[mt], bh);
                }
    }

    const int er0 = lane >> 2, ec = (lane & 3) * 2;
#pragma unroll
    for (int mt = 0; mt < 2; mt++)
#pragma unroll
        for (int nt = 0; nt < 4; nt++) {
            int b0 = warpM * 32 + mt * 16 + er0;
            int co = cobase + warpN * 32 + nt * 8 + ec;
            float* p0 = &g_uhat[((size_t)b0 * NR + r) * NCO + co];
            float* p1 = &g_uhat[((size_t)(b0 + 8) * NR + r) * NCO + co];
            *(float2*)p0 = make_float2(acc[mt][nt][0], acc[mt][nt][1]);
            *(float2*)p1 = make_float2(acc[mt][nt][2], acc[mt][nt][3]);
        }
}

// ---------------------------------------------------------------------------
// K2a: pass-0 sum (uniform weights): s0[b,co] = Sum_r u / 32, no softmax.
// grid (B, RCH), 256 threads; thread t owns co-quad 4t. Pure coalesced BW.
// ---------------------------------------------------------------------------
__global__ void __launch_bounds__(256)
k_sum0() {
    const int b = blockIdx.x, ch = blockIdx.y, t = threadIdx.x;
    const float4* up = (const float4*)g_uhat + ((size_t)b * NR + ch * RPC) * (NCO / 4) + t;
    float4 s = make_float4(0.f, 0.f, 0.f, 0.f);
#pragma unroll 8
    for (int rr = 0; rr < RPC; rr++) {
        float4 u = up[(size_t)rr * (NCO / 4)];
        s.x += u.x; s.y += u.y; s.z += u.z; s.w += u.w;
    }
    ((float4*)g_spart)[((size_t)ch * NB + b) * (NCO / 4) + t] = s;
}

// ---------------------------------------------------------------------------
// K2b: routing pass (Vacc logits). grid (B, RCH), 256 threads.
// Thread t owns co-quad 4t (coalesced); c = t>>3. Next-r prefetch issued
// before the softmax barriers so DRAM latency overlaps the reduction.
// ---------------------------------------------------------------------------
__global__ void __launch_bounds__(256)
k_route() {
    const int b = blockIdx.x, ch = blockIdx.y, t = threadIdx.x;
    __shared__ float sm_a[NC], sm_w[NC];
    const float4* up = (const float4*)g_uhat + ((size_t)b * NR + ch * RPC) * (NCO / 4) + t;
    float4 vv = ((const float4*)g_vacc)[b * (NCO / 4) + t];
    float4 acc = make_float4(0.f, 0.f, 0.f, 0.f);
    float4 u = up[0];
    for (int rr = 0; rr < RPC; rr++) {
        float4 cu = u;
        if (rr + 1 < RPC) u = up[(size_t)(rr + 1) * (NCO / 4)];  // prefetch
        float p = cu.x * vv.x + cu.y * vv.y + cu.z * vv.z + cu.w * vv.w;
        p += __shfl_xor_sync(0xffffffffu, p, 1);
        p += __shfl_xor_sync(0xffffffffu, p, 2);
        p += __shfl_xor_sync(0xffffffffu, p, 4);
        if ((t & 7) == 0) sm_a[t >> 3] = p;
        __syncthreads();
        if (t < 32) {
            float av = sm_a[t], mx = av;
#pragma unroll
            for (int s = 16; s; s >>= 1) mx = fmaxf(mx, __shfl_xor_sync(0xffffffffu, mx, s));
            float e = __expf(av - mx), sum = e;
#pragma unroll
            for (int s = 16; s; s >>= 1) sum += __shfl_xor_sync(0xffffffffu, sum, s);
            sm_w[t] = e / sum;
        }
        __syncthreads();
        float wgt = sm_w[t >> 3];
        acc.x = fmaf(wgt, cu.x, acc.x);
        acc.y = fmaf(wgt, cu.y, acc.y);
        acc.z = fmaf(wgt, cu.z, acc.z);
        acc.w = fmaf(wgt, cu.w, acc.w);
    }
    ((float4*)g_spart)[((size_t)ch * NB + b) * (NCO / 4) + t] = acc;
}

// ---------------------------------------------------------------------------
// K3: reduce over chunks, squash per (b,c), update Vacc / write out.
// scl = 1/32 for iter 0 (uniform weights), 1 otherwise.
// ---------------------------------------------------------------------------
__global__ void __launch_bounds__(256)
k_squash(float* __restrict__ out, int iter, float scl) {
    const int b = blockIdx.x, t = threadIdx.x;
    float4 s = make_float4(0.f, 0.f, 0.f, 0.f);
    const float4* sp = (const float4*)g_spart + (size_t)b * (NCO / 4) + t;
#pragma unroll 4
    for (int ch = 0; ch < RCH; ch++) {
        float4 p = sp[(size_t)ch * NB * (NCO / 4)];
        s.x += p.x; s.y += p.y; s.z += p.z; s.w += p.w;
    }
    s.x *= scl; s.y *= scl; s.z *= scl; s.w *= scl;
    float ss = s.x * s.x + s.y * s.y + s.z * s.z + s.w * s.w;
    ss += __shfl_xor_sync(0xffffffffu, ss, 1);
    ss += __shfl_xor_sync(0xffffffffu, ss, 2);
    ss += __shfl_xor_sync(0xffffffffu, ss, 4);
    float norm = sqrtf(ss);
    float scale = ss / (1.0f + ss) / (norm + 1e-8f);
    float4 v = make_float4(s.x * scale, s.y * scale, s.z * scale, s.w * scale);
    float4* va = (float4*)g_vacc + b * (NCO / 4) + t;
    if (iter == 2) ((float4*)out)[b * (NCO / 4) + t] = v;
    else if (iter == 0) *va = v;
    else { float4 a = *va; a.x += v.x; a.y += v.y; a.z += v.z; a.w += v.w; *va = a; }
}

extern "C" void kernel_launch(void* const* d_in, const int* in_sizes, int n_in,
                              void* d_out, int out_size) {
    const float* x = (const float*)d_in[0];  // [B,R,I]
    const float* W = (const float*)d_in[1];  // [R,C,O,I]
    float* out = (float*)d_out;              // [B,C,O]
    k_uhat<<<dim3(16, NR), 256>>>(x, W);
    k_sum0<<<dim3(NB, RCH), 256>>>();
    k_squash<<<NB, 256>>>(out, 0, 1.0f / 32.0f);
    k_route<<<dim3(NB, RCH), 256>>>();
    k_squash<<<NB, 256>>>(out, 1, 1.0f);
    k_route<<<dim3(NB, RCH), 256>>>();
    k_squash<<<NB, 256>>>(out, 2, 1.0f);
}

// round 12
// speedup vs baseline: 3.2154x; 1.0205x over previous
#include <cuda_runtime.h>
#include <cuda_bf16.h>
#include <cstdint>

#define NB 128
#define NR 1152
#define NC 32
#define NI 64
#define NCO 1024
#define RPC 32
#define RCH 36

__device__ float g_uhat[(size_t)NB * NR * NCO];    // [b][r][co] ~604 MB
__device__ float g_spart[(size_t)RCH * NB * NCO];  // [ch][b][co]
__device__ float g_vacc[(size_t)NB * NCO];
// pre-converted x tiles: per r, 128x64 bf16 in the smem-swizzled layout
__device__ __nv_bfloat16 g_xh[(size_t)NR * 8192];  // 18.9 MB
__device__ __nv_bfloat16 g_xl[(size_t)NR * 8192];

__device__ __forceinline__ unsigned su32(const void* p) {
    unsigned a;
    asm("{ .reg .u64 t; cvta.to.shared.u64 t,%1; cvt.u32.u64 %0,t; }" : "=r"(a) : "l"(p));
    return a;
}
__device__ __forceinline__ void ldm4(unsigned* r, unsigned a) {
    asm volatile("ldmatrix.sync.aligned.m8n8.x4.shared.b16 {%0,%1,%2,%3}, [%4];"
                 : "=r"(r[0]), "=r"(r[1]), "=r"(r[2]), "=r"(r[3]) : "r"(a));
}
__device__ __forceinline__ void mma16816(float* d, const unsigned* a, const unsigned* b) {
    asm volatile(
        "mma.sync.aligned.m16n8k16.row.col.f32.bf16.bf16.f32 "
        "{%0,%1,%2,%3}, {%4,%5,%6,%7}, {%8,%9}, {%0,%1,%2,%3};"
        : "+f"(d[0]), "+f"(d[1]), "+f"(d[2]), "+f"(d[3])
        : "r"(a[0]), "r"(a[1]), "r"(a[2]), "r"(a[3]), "r"(b[0]), "r"(b[1]));
}
// split 8 fp32 -> hi/lo bf16 uint4 pair
__device__ __forceinline__ void split8(const float4 f0, const float4 f1,
                                       uint4& H, uint4& L) {
    float a[8] = {f0.x, f0.y, f0.z, f0.w, f1.x, f1.y, f1.z, f1.w};
    unsigned hv[4], lv[4];
#pragma unroll
    for (int j = 0; j < 4; j++) {
        __nv_bfloat162 h = __floats2bfloat162_rn(a[2 * j], a[2 * j + 1]);
        float r0 = a[2 * j] - __bfloat162float(h.x);
        float r1 = a[2 * j + 1] - __bfloat162float(h.y);
        __nv_bfloat162 l = __floats2bfloat162_rn(r0, r1);
        hv[j] = *(unsigned*)&h;
        lv[j] = *(unsigned*)&l;
    }
    H = make_uint4(hv[0], hv[1], hv[2], hv[3]);
    L = make_uint4(lv[0], lv[1], lv[2], lv[3]);
}

// ---------------------------------------------------------------------------
// K0: pre-convert x -> swizzled bf16 hi/lo tiles (one per r). grid (NR).
// ---------------------------------------------------------------------------
__global__ void __launch_bounds__(256)
k_xconv(const float* __restrict__ x) {
    const int r = blockIdx.x, tid = threadIdx.x;
    uint4* dh = (uint4*)(g_xh + (size_t)r * 8192);
    uint4* dl = (uint4*)(g_xl + (size_t)r * 8192);
    for (int i = tid; i < 1024; i += 256) {
        int row = i >> 3, c = i & 7;
        const float* p = x + ((size_t)row * NR + r) * NI + c * 8;
        uint4 H, L;
        split8(*(const float4*)p, *(const float4*)(p + 4), H, L);
        unsigned o = row * 8 + (c ^ (row & 7));  // uint4 index (swizzled)
        dh[o] = H;
        dl[o] = L;
    }
}

// ---------------------------------------------------------------------------
// K1: u_hat GEMM via bf16 mma.sync, 3-term hi/lo split.
// grid (16 co-chunks, 1152 r). CTA tile M=128(b) x N=64(co) x K=64(i).
// x tiles copied pre-converted; W converted inline.
// ---------------------------------------------------------------------------
__global__ void __launch_bounds__(256)
k_uhat(const float* __restrict__ W) {
    __shared__ __align__(16) __nv_bfloat16 xh[NB * NI], xl[NB * NI];
    __shared__ __align__(16) __nv_bfloat16 wh[64 * NI], wl[64 * NI];
    const int cobase = blockIdx.x * 64;
    const int r = blockIdx.y;
    const int tid = threadIdx.x, wid = tid >> 5, lane = tid & 31;

    // x: straight uint4 copy of pre-swizzled bf16 (L2-shared across 16 CTAs)
    {
        const uint4* sh = (const uint4*)(g_xh + (size_t)r * 8192);
        const uint4* sl = (const uint4*)(g_xl + (size_t)r * 8192);
        uint4* dh = (uint4*)xh;
        uint4* dl = (uint4*)xl;
        for (int i = tid; i < 1024; i += 256) {
            dh[i] = sh[i];
            dl[i] = sl[i];
        }
    }
    // W: inline split-convert
    for (int i = tid; i < 512; i += 256) {
        int row = i >> 3, c = i & 7;
        const float* p = W + ((size_t)r * NCO + cobase + row) * NI + c * 8;
        uint4 H, L;
        split8(*(const float4*)p, *(const float4*)(p + 4), H, L);
        unsigned o = row * 8 + (c ^ (row & 7));
        ((uint4*)wh)[o] = H;
        ((uint4*)wl)[o] = L;
    }
    __syncthreads();

    const int warpM = wid >> 1, warpN = wid & 1;
    const int lrow = (lane & 7) + ((lane >> 3) & 1) * 8;
    const unsigned csel = lane >> 4;
    unsigned arow[2], brow[2];
#pragma unroll
    for (int mt = 0; mt < 2; mt++) arow[mt] = (warpM * 32 + mt * 16 + lrow);
#pragma unroll
    for (int np = 0; np < 2; np++) brow[np] = (warpN * 32 + np * 16 + lrow);

    float acc[2][4][4];
#pragma unroll
    for (int mt = 0; mt < 2; mt++)
#pragma unroll
        for (int nt = 0; nt < 4; nt++)
#pragma unroll
            for (int j = 0; j < 4; j++) acc[mt][nt][j] = 0.f;

    const unsigned bxh = su32(xh), bxl = su32(xl);
    const unsigned bwh = su32(wh), bwl = su32(wl);

#pragma unroll
    for (int kk = 0; kk < 4; kk++) {
        unsigned Ah[2][4], Al[2][4], Bh[2][4], Bl[2][4];
#pragma unroll
        for (int mt = 0; mt < 2; mt++) {
            unsigned rs = arow[mt] & 7;
            unsigned off = arow[mt] * 128u + (((2u * kk + csel) ^ rs) << 4);
            ldm4(Ah[mt], bxh + off);
            ldm4(Al[mt], bxl + off);
        }
#pragma unroll
        for (int np = 0; np < 2; np++) {
            unsigned rs = brow[np] & 7;
            unsigned off = brow[np] * 128u + (((2u * kk + csel) ^ rs) << 4);
            ldm4(Bh[np], bwh + off);
            ldm4(Bl[np], bwl + off);
        }
#pragma unroll
        for (int mt = 0; mt < 2; mt++)
#pragma unroll
            for (int np = 0; np < 2; np++)
#pragma unroll
                for (int sub = 0; sub < 2; sub++) {
                    unsigned bh[2] = {Bh[np][sub], Bh[np][sub + 2]};
                    unsigned bl[2] = {Bl[np][sub], Bl[np][sub + 2]};
                    float* d = acc[mt][np * 2 + sub];
                    mma16816(d, Ah[mt], bh);
                    mma16816(d, Ah[mt], bl);
                    mma16816(d, Al[mt], bh);
                }
    }

    const int er0 = lane >> 2, ec = (lane & 3) * 2;
#pragma unroll
    for (int mt = 0; mt < 2; mt++)
#pragma unroll
        for (int nt = 0; nt < 4; nt++) {
            int b0 = warpM * 32 + mt * 16 + er0;
            int co = cobase + warpN * 32 + nt * 8 + ec;
            float* p0 = &g_uhat[((size_t)b0 * NR + r) * NCO + co];
            float* p1 = &g_uhat[((size_t)(b0 + 8) * NR + r) * NCO + co];
            *(float2*)p0 = make_float2(acc[mt][nt][0], acc[mt][nt][1]);
            *(float2*)p1 = make_float2(acc[mt][nt][2], acc[mt][nt][3]);
        }
}

// ---------------------------------------------------------------------------
// K2a: pass-0 sum (uniform weights). grid (B, RCH), coalesced float4 sum.
// ---------------------------------------------------------------------------
__global__ void __launch_bounds__(256)
k_sum0() {
    const int b = blockIdx.x, ch = blockIdx.y, t = threadIdx.x;
    const float4* up = (const float4*)g_uhat + ((size_t)b * NR + ch * RPC) * (NCO / 4) + t;
    float4 s = make_float4(0.f, 0.f, 0.f, 0.f);
#pragma unroll 8
    for (int rr = 0; rr < RPC; rr++) {
        float4 u = up[(size_t)rr * (NCO / 4)];
        s.x += u.x; s.y += u.y; s.z += u.z; s.w += u.w;
    }
    ((float4*)g_spart)[((size_t)ch * NB + b) * (NCO / 4) + t] = s;
}

// ---------------------------------------------------------------------------
// K2b: routing pass, 2 r's per iteration (half the barriers, 2 loads in
// flight; softmax rows done by two warps in parallel). grid (B, RCH).
// ---------------------------------------------------------------------------
__global__ void __launch_bounds__(256)
k_route() {
    const int b = blockIdx.x, ch = blockIdx.y, t = threadIdx.x;
    __shared__ float sm_a[2 * NC], sm_w[2 * NC];
    const float4* up = (const float4*)g_uhat + ((size_t)b * NR + ch * RPC) * (NCO / 4) + t;
    float4 vv = ((const float4*)g_vacc)[b * (NCO / 4) + t];
    float4 acc = make_float4(0.f, 0.f, 0.f, 0.f);
    float4 u0 = up[0], u1 = up[NCO / 4];
    for (int rr = 0; rr < RPC; rr += 2) {
        float4 a0 = u0, a1 = u1;
        if (rr + 2 < RPC) {  // prefetch next pair before the barriers
            u0 = up[(size_t)(rr + 2) * (NCO / 4)];
            u1 = up[(size_t)(rr + 3) * (NCO / 4)];
        }
        float p0 = a0.x * vv.x + a0.y * vv.y + a0.z * vv.z + a0.w * vv.w;
        float p1 = a1.x * vv.x + a1.y * vv.y + a1.z * vv.z + a1.w * vv.w;
#pragma unroll
        for (int s = 4; s; s >>= 1) {
            p0 += __shfl_xor_sync(0xffffffffu, p0, s);
            p1 += __shfl_xor_sync(0xffffffffu, p1, s);
        }
        if ((t & 7) == 0) {
            sm_a[t >> 3] = p0;
            sm_a[NC + (t >> 3)] = p1;
        }
        __syncthreads();
        if (t < 64) {  // warp0 -> row0, warp1 -> row1
            float av = sm_a[t], mx = av;
#pragma unroll
            for (int s = 16; s; s >>= 1) mx = fmaxf(mx, __shfl_xor_sync(0xffffffffu, mx, s));
            float e = __expf(av - mx), sum = e;
#pragma unroll
            for (int s = 16; s; s >>= 1) sum += __shfl_xor_sync(0xffffffffu, sum, s);
            sm_w[t] = e / sum;
        }
        __syncthreads();
        float w0 = sm_w[t >> 3], w1 = sm_w[NC + (t >> 3)];
        acc.x += w0 * a0.x + w1 * a1.x;
        acc.y += w0 * a0.y + w1 * a1.y;
        acc.z += w0 * a0.z + w1 * a1.z;
        acc.w += w0 * a0.w + w1 * a1.w;
    }
    ((float4*)g_spart)[((size_t)ch * NB + b) * (NCO / 4) + t] = acc;
}

// ---------------------------------------------------------------------------
// K3: reduce over chunks, squash, update Vacc / write out.
// ---------------------------------------------------------------------------
__global__ void __launch_bounds__(256)
k_squash(float* __restrict__ out, int iter, float scl) {
    const int b = blockIdx.x, t = threadIdx.x;
    float4 s = make_float4(0.f, 0.f, 0.f, 0.f);
    const float4* sp = (const float4*)g_spart + (size_t)b * (NCO / 4) + t;
#pragma unroll 4
    for (int ch = 0; ch < RCH; ch++) {
        float4 p = sp[(size_t)ch * NB * (NCO / 4)];
        s.x += p.x; s.y += p.y; s.z += p.z; s.w += p.w;
    }
    s.x *= scl; s.y *= scl; s.z *= scl; s.w *= scl;
    float ss = s.x * s.x + s.y * s.y + s.z * s.z + s.w * s.w;
    ss += __shfl_xor_sync(0xffffffffu, ss, 1);
    ss += __shfl_xor_sync(0xffffffffu, ss, 2);
    ss += __shfl_xor_sync(0xffffffffu, ss, 4);
    float norm = sqrtf(ss);
    float scale = ss / (1.0f + ss) / (norm + 1e-8f);
    float4 v = make_float4(s.x * scale, s.y * scale, s.z * scale, s.w * scale);
    float4* va = (float4*)g_vacc + b * (NCO / 4) + t;
    if (iter == 2) ((float4*)out)[b * (NCO / 4) + t] = v;
    else if (iter == 0) *va = v;
    else { float4 a = *va; a.x += v.x; a.y += v.y; a.z += v.z; a.w += v.w; *va = a; }
}

extern "C" void kernel_launch(void* const* d_in, const int* in_sizes, int n_in,
                              void* d_out, int out_size) {
    const float* x = (const float*)d_in[0];  // [B,R,I]
    const float* W = (const float*)d_in[1];  // [R,C,O,I]
    float* out = (float*)d_out;              // [B,C,O]
    k_xconv<<<NR, 256>>>(x);
    k_uhat<<<dim3(16, NR), 256>>>(W);
    k_sum0<<<dim3(NB, RCH), 256>>>();
    k_squash<<<NB, 256>>>(out, 0, 1.0f / 32.0f);
    k_route<<<dim3(NB, RCH), 256>>>();
    k_squash<<<NB, 256>>>(out, 1, 1.0f);
    k_route<<<dim3(NB, RCH), 256>>>();
    k_squash<<<NB, 256>>>(out, 2, 1.0f);
}

// round 15
// speedup vs baseline: 3.8526x; 1.1982x over previous
#include <cuda_runtime.h>
#include <cuda_bf16.h>
#include <cuda_fp16.h>
#include <cstdint>

#define NB 128
#define NR 1152
#define NC 32
#define NI 64
#define NCO 1024
#define RPC 32
#define RCH 36

__device__ __half g_uhat[(size_t)NB * NR * NCO];   // [b][r][co] ~302 MB (fp16)
__device__ float g_spart[(size_t)RCH * NB * NCO];  // [ch][b][co] fp32
__device__ float g_vacc[(size_t)NB * NCO];
// pre-converted x tiles: per r, 128x64 bf16 in the smem-swizzled layout
__device__ __nv_bfloat16 g_xh[(size_t)NR * 8192];
__device__ __nv_bfloat16 g_xl[(size_t)NR * 8192];

__device__ __forceinline__ unsigned su32(const void* p) {
    unsigned a;
    asm("{ .reg .u64 t; cvta.to.shared.u64 t,%1; cvt.u32.u64 %0,t; }" : "=r"(a) : "l"(p));
    return a;
}
__device__ __forceinline__ void ldm4(unsigned* r, unsigned a) {
    asm volatile("ldmatrix.sync.aligned.m8n8.x4.shared.b16 {%0,%1,%2,%3}, [%4];"
                 : "=r"(r[0]), "=r"(r[1]), "=r"(r[2]), "=r"(r[3]) : "r"(a));
}
__device__ __forceinline__ void mma16816(float* d, const unsigned* a, const unsigned* b) {
    asm volatile(
        "mma.sync.aligned.m16n8k16.row.col.f32.bf16.bf16.f32 "
        "{%0,%1,%2,%3}, {%4,%5,%6,%7}, {%8,%9}, {%0,%1,%2,%3};"
        : "+f"(d[0]), "+f"(d[1]), "+f"(d[2]), "+f"(d[3])
        : "r"(a[0]), "r"(a[1]), "r"(a[2]), "r"(a[3]), "r"(b[0]), "r"(b[1]));
}
__device__ __forceinline__ void split8(const float4 f0, const float4 f1,
                                       uint4& H, uint4& L) {
    float a[8] = {f0.x, f0.y, f0.z, f0.w, f1.x, f1.y, f1.z, f1.w};
    unsigned hv[4], lv[4];
#pragma unroll
    for (int j = 0; j < 4; j++) {
        __nv_bfloat162 h = __floats2bfloat162_rn(a[2 * j], a[2 * j + 1]);
        float r0 = a[2 * j] - __bfloat162float(h.x);
        float r1 = a[2 * j + 1] - __bfloat162float(h.y);
        __nv_bfloat162 l = __floats2bfloat162_rn(r0, r1);
        hv[j] = *(unsigned*)&h;
        lv[j] = *(unsigned*)&l;
    }
    H = make_uint4(hv[0], hv[1], hv[2], hv[3]);
    L = make_uint4(lv[0], lv[1], lv[2], lv[3]);
}

// ---------------------------------------------------------------------------
// K0: pre-convert x -> swizzled bf16 hi/lo tiles (one per r). grid (NR).
// ---------------------------------------------------------------------------
__global__ void __launch_bounds__(256)
k_xconv(const float* __restrict__ x) {
    const int r = blockIdx.x, tid = threadIdx.x;
    uint4* dh = (uint4*)(g_xh + (size_t)r * 8192);
    uint4* dl = (uint4*)(g_xl + (size_t)r * 8192);
    for (int i = tid; i < 1024; i += 256) {
        int row = i >> 3, c = i & 7;
        const float* p = x + ((size_t)row * NR + r) * NI + c * 8;
        uint4 H, L;
        split8(*(const float4*)p, *(const float4*)(p + 4), H, L);
        unsigned o = row * 8 + (c ^ (row & 7));
        dh[o] = H;
        dl[o] = L;
    }
}

// ---------------------------------------------------------------------------
// K1: u_hat GEMM via bf16 mma.sync, 3-term hi/lo split. fp16 output.
// grid (16 co-chunks, 1152 r). CTA tile M=128(b) x N=64(co) x K=64(i).
// ---------------------------------------------------------------------------
__global__ void __launch_bounds__(256)
k_uhat(const float* __restrict__ W) {
    __shared__ __align__(16) __nv_bfloat16 xh[NB * NI], xl[NB * NI];
    __shared__ __align__(16) __nv_bfloat16 wh[64 * NI], wl[64 * NI];
    const int cobase = blockIdx.x * 64;
    const int r = blockIdx.y;
    const int tid = threadIdx.x, wid = tid >> 5, lane = tid & 31;

    {
        const uint4* sh = (const uint4*)(g_xh + (size_t)r * 8192);
        const uint4* sl = (const uint4*)(g_xl + (size_t)r * 8192);
        uint4* dh = (uint4*)xh;
        uint4* dl = (uint4*)xl;
        for (int i = tid; i < 1024; i += 256) {
            dh[i] = sh[i];
            dl[i] = sl[i];
        }
    }
    for (int i = tid; i < 512; i += 256) {
        int row = i >> 3, c = i & 7;
        const float* p = W + ((size_t)r * NCO + cobase + row) * NI + c * 8;
        uint4 H, L;
        split8(*(const float4*)p, *(const float4*)(p + 4), H, L);
        unsigned o = row * 8 + (c ^ (row & 7));
        ((uint4*)wh)[o] = H;
        ((uint4*)wl)[o] = L;
    }
    __syncthreads();

    const int warpM = wid >> 1, warpN = wid & 1;
    const int lrow = (lane & 7) + ((lane >> 3) & 1) * 8;
    const unsigned csel = lane >> 4;
    unsigned arow[2], brow[2];
#pragma unroll
    for (int mt = 0; mt < 2; mt++) arow[mt] = (warpM * 32 + mt * 16 + lrow);
#pragma unroll
    for (int np = 0; np < 2; np++) brow[np] = (warpN * 32 + np * 16 + lrow);

    float acc[2][4][4];
#pragma unroll
    for (int mt = 0; mt < 2; mt++)
#pragma unroll
        for (int nt = 0; nt < 4; nt++)
#pragma unroll
            for (int j = 0; j < 4; j++) acc[mt][nt][j] = 0.f;

    const unsigned bxh = su32(xh), bxl = su32(xl);
    const unsigned bwh = su32(wh), bwl = su32(wl);

#pragma unroll
    for (int kk = 0; kk < 4; kk++) {
        unsigned Ah[2][4], Al[2][4], Bh[2][4], Bl[2][4];
#pragma unroll
        for (int mt = 0; mt < 2; mt++) {
            unsigned rs = arow[mt] & 7;
            unsigned off = arow[mt] * 128u + (((2u * kk + csel) ^ rs) << 4);
            ldm4(Ah[mt], bxh + off);
            ldm4(Al[mt], bxl + off);
        }
#pragma unroll
        for (int np = 0; np < 2; np++) {
            unsigned rs = brow[np] & 7;
            unsigned off = brow[np] * 128u + (((2u * kk + csel) ^ rs) << 4);
            ldm4(Bh[np], bwh + off);
            ldm4(Bl[np], bwl + off);
        }
#pragma unroll
        for (int mt = 0; mt < 2; mt++)
#pragma unroll
            for (int np = 0; np < 2; np++)
#pragma unroll
                for (int sub = 0; sub < 2; sub++) {
                    unsigned bh[2] = {Bh[np][sub], Bh[np][sub + 2]};
                    unsigned bl[2] = {Bl[np][sub], Bl[np][sub + 2]};
                    float* d = acc[mt][np * 2 + sub];
                    mma16816(d, Ah[mt], bh);
                    mma16816(d, Ah[mt], bl);
                    mma16816(d, Al[mt], bh);
                }
    }

    // epilogue: fp16 stores (half2 per fragment row pair)
    const int er0 = lane >> 2, ec = (lane & 3) * 2;
#pragma unroll
    for (int mt = 0; mt < 2; mt++)
#pragma unroll
        for (int nt = 0; nt < 4; nt++) {
            int b0 = warpM * 32 + mt * 16 + er0;
            int co = cobase + warpN * 32 + nt * 8 + ec;
            __half* p0 = &g_uhat[((size_t)b0 * NR + r) * NCO + co];
            __half* p1 = &g_uhat[((size_t)(b0 + 8) * NR + r) * NCO + co];
            *(__half2*)p0 = __floats2half2_rn(acc[mt][nt][0], acc[mt][nt][1]);
            *(__half2*)p1 = __floats2half2_rn(acc[mt][nt][2], acc[mt][nt][3]);
        }
}

// load 4 consecutive halfs (8B) -> float4
__device__ __forceinline__ float4 ld_h4(const __half* p) {
    uint2 v = *(const uint2*)p;
    float2 f0 = __half22float2(*(__half2*)&v.x);
    float2 f1 = __half22float2(*(__half2*)&v.y);
    return make_float4(f0.x, f0.y, f1.x, f1.y);
}

// ---------------------------------------------------------------------------
// K2a: pass-0 sum (uniform weights). grid (B, RCH); thread owns co-quad.
// ---------------------------------------------------------------------------
__global__ void __launch_bounds__(256)
k_sum0() {
    const int b = blockIdx.x, ch = blockIdx.y, t = threadIdx.x;
    const __half* up = g_uhat + ((size_t)b * NR + ch * RPC) * NCO + t * 4;
    float4 s = make_float4(0.f, 0.f, 0.f, 0.f);
#pragma unroll 8
    for (int rr = 0; rr < RPC; rr++) {
        float4 u = ld_h4(up + (size_t)rr * NCO);
        s.x += u.x; s.y += u.y; s.z += u.z; s.w += u.w;
    }
    ((float4*)g_spart)[((size_t)ch * NB + b) * (NCO / 4) + t] = s;
}

// ---------------------------------------------------------------------------
// K2b: routing pass, 2 r's per iteration, prefetch across barriers.
// ---------------------------------------------------------------------------
__global__ void __launch_bounds__(256)
k_route() {
    const int b = blockIdx.x, ch = blockIdx.y, t = threadIdx.x;
    __shared__ float sm_a[2 * NC], sm_w[2 * NC];
    const __half* up = g_uhat + ((size_t)b * NR + ch * RPC) * NCO + t * 4;
    float4 vv = ((const float4*)g_vacc)[b * (NCO / 4) + t];
    float4 acc = make_float4(0.f, 0.f, 0.f, 0.f);
    float4 u0 = ld_h4(up), u1 = ld_h4(up + NCO);
    for (int rr = 0; rr < RPC; rr += 2) {
        float4 a0 = u0, a1 = u1;
        if (rr + 2 < RPC) {
            u0 = ld_h4(up + (size_t)(rr + 2) * NCO);
            u1 = ld_h4(up + (size_t)(rr + 3) * NCO);
        }
        float p0 = a0.x * vv.x + a0.y * vv.y + a0.z * vv.z + a0.w * vv.w;
        float p1 = a1.x * vv.x + a1.y * vv.y + a1.z * vv.z + a1.w * vv.w;
#pragma unroll
        for (int s = 4; s; s >>= 1) {
            p0 += __shfl_xor_sync(0xffffffffu, p0, s);
            p1 += __shfl_xor_sync(0xffffffffu, p1, s);
        }
        if ((t & 7) == 0) {
            sm_a[t >> 3] = p0;
            sm_a[NC + (t >> 3)] = p1;
        }
        __syncthreads();
        if (t < 64) {
            float av = sm_a[t], mx = av;
#pragma unroll
            for (int s = 16; s; s >>= 1) mx = fmaxf(mx, __shfl_xor_sync(0xffffffffu, mx, s));
            float e = __expf(av - mx), sum = e;
#pragma unroll
            for (int s = 16; s; s >>= 1) sum += __shfl_xor_sync(0xffffffffu, sum, s);
            sm_w[t] = e / sum;
        }
        __syncthreads();
        float w0 = sm_w[t >> 3], w1 = sm_w[NC + (t >> 3)];
        acc.x += w0 * a0.x + w1 * a1.x;
        acc.y += w0 * a0.y + w1 * a1.y;
        acc.z += w0 * a0.z + w1 * a1.z;
        acc.w += w0 * a0.w + w1 * a1.w;
    }
    ((float4*)g_spart)[((size_t)ch * NB + b) * (NCO / 4) + t] = acc;
}

// ---------------------------------------------------------------------------
// K3: reduce over chunks, squash, update Vacc / write out.
// ---------------------------------------------------------------------------
__global__ void __launch_bounds__(256)
k_squash(float* __restrict__ out, int iter, float scl) {
    const int b = blockIdx.x, t = threadIdx.x;
    float4 s = make_float4(0.f, 0.f, 0.f, 0.f);
    const float4* sp = (const float4*)g_spart + (size_t)b * (NCO / 4) + t;
#pragma unroll 4
    for (int ch = 0; ch < RCH; ch++) {
        float4 p = sp[(size_t)ch * NB * (NCO / 4)];
        s.x += p.x; s.y += p.y; s.z += p.z; s.w += p.w;
    }
    s.x *= scl; s.y *= scl; s.z *= scl; s.w *= scl;
    float ss = s.x * s.x + s.y * s.y + s.z * s.z + s.w * s.w;
    ss += __shfl_xor_sync(0xffffffffu, ss, 1);
    ss += __shfl_xor_sync(0xffffffffu, ss, 2);
    ss += __shfl_xor_sync(0xffffffffu, ss, 4);
    float norm = sqrtf(ss);
    float scale = ss / (1.0f + ss) / (norm + 1e-8f);
    float4 v = make_float4(s.x * scale, s.y * scale, s.z * scale, s.w * scale);
    float4* va = (float4*)g_vacc + b * (NCO / 4) + t;
    if (iter == 2) ((float4*)out)[b * (NCO / 4) + t] = v;
    else if (iter == 0) *va = v;
    else { float4 a = *va; a.x += v.x; a.y += v.y; a.z += v.z; a.w += v.w; *va = a; }
}

extern "C" void kernel_launch(void* const* d_in, const int* in_sizes, int n_in,
                              void* d_out, int out_size) {
    const float* x = (const float*)d_in[0];  // [B,R,I]
    const float* W = (const float*)d_in[1];  // [R,C,O,I]
    float* out = (float*)d_out;              // [B,C,O]
    k_xconv<<<NR, 256>>>(x);
    k_uhat<<<dim3(16, NR), 256>>>(W);
    k_sum0<<<dim3(NB, RCH), 256>>>();
    k_squash<<<NB, 256>>>(out, 0, 1.0f / 32.0f);
    k_route<<<dim3(NB, RCH), 256>>>();
    k_squash<<<NB, 256>>>(out, 1, 1.0f);
    k_route<<<dim3(NB, RCH), 256>>>();
    k_squash<<<NB, 256>>>(out, 2, 1.0f);
}

// round 16
// speedup vs baseline: 3.8719x; 1.0050x over previous
#include <cuda_runtime.h>
#include <cuda_bf16.h>
#include <cuda_fp16.h>
#include <cstdint>

#define NB 128
#define NR 1152
#define NC 32
#define NI 64
#define NCO 1024
#define RPC 32
#define RCH 36

__device__ __half g_uhat[(size_t)NB * NR * NCO];   // [b][r][co] ~302 MB (fp16)
__device__ float g_spart[(size_t)RCH * NB * NCO];  // [ch][b][co] fp32
__device__ float g_vacc[(size_t)NB * NCO];
// pre-converted x tiles: per r, 128x64 bf16 in the smem-swizzled layout
__device__ __nv_bfloat16 g_xh[(size_t)NR * 8192];
__device__ __nv_bfloat16 g_xl[(size_t)NR * 8192];

__device__ __forceinline__ unsigned su32(const void* p) {
    unsigned a;
    asm("{ .reg .u64 t; cvta.to.shared.u64 t,%1; cvt.u32.u64 %0,t; }" : "=r"(a) : "l"(p));
    return a;
}
__device__ __forceinline__ void ldm4(unsigned* r, unsigned a) {
    asm volatile("ldmatrix.sync.aligned.m8n8.x4.shared.b16 {%0,%1,%2,%3}, [%4];"
                 : "=r"(r[0]), "=r"(r[1]), "=r"(r[2]), "=r"(r[3]) : "r"(a));
}
__device__ __forceinline__ void mma16816(float* d, const unsigned* a, const unsigned* b) {
    asm volatile(
        "mma.sync.aligned.m16n8k16.row.col.f32.bf16.bf16.f32 "
        "{%0,%1,%2,%3}, {%4,%5,%6,%7}, {%8,%9}, {%0,%1,%2,%3};"
        : "+f"(d[0]), "+f"(d[1]), "+f"(d[2]), "+f"(d[3])
        : "r"(a[0]), "r"(a[1]), "r"(a[2]), "r"(a[3]), "r"(b[0]), "r"(b[1]));
}
__device__ __forceinline__ void split8(const float4 f0, const float4 f1,
                                       uint4& H, uint4& L) {
    float a[8] = {f0.x, f0.y, f0.z, f0.w, f1.x, f1.y, f1.z, f1.w};
    unsigned hv[4], lv[4];
#pragma unroll
    for (int j = 0; j < 4; j++) {
        __nv_bfloat162 h = __floats2bfloat162_rn(a[2 * j], a[2 * j + 1]);
        float r0 = a[2 * j] - __bfloat162float(h.x);
        float r1 = a[2 * j + 1] - __bfloat162float(h.y);
        __nv_bfloat162 l = __floats2bfloat162_rn(r0, r1);
        hv[j] = *(unsigned*)&h;
        lv[j] = *(unsigned*)&l;
    }
    H = make_uint4(hv[0], hv[1], hv[2], hv[3]);
    L = make_uint4(lv[0], lv[1], lv[2], lv[3]);
}

// ---------------------------------------------------------------------------
// K0: pre-convert x -> swizzled bf16 hi/lo tiles. Launched as 5 r-slices so
// that k_uhat is the 6th kernel launch (the one ncu samples).
// ---------------------------------------------------------------------------
__global__ void __launch_bounds__(256)
k_xconv(const float* __restrict__ x, int roff) {
    const int r = blockIdx.x + roff, tid = threadIdx.x;
    uint4* dh = (uint4*)(g_xh + (size_t)r * 8192);
    uint4* dl = (uint4*)(g_xl + (size_t)r * 8192);
    for (int i = tid; i < 1024; i += 256) {
        int row = i >> 3, c = i & 7;
        const float* p = x + ((size_t)row * NR + r) * NI + c * 8;
        uint4 H, L;
        split8(*(const float4*)p, *(const float4*)(p + 4), H, L);
        unsigned o = row * 8 + (c ^ (row & 7));
        dh[o] = H;
        dl[o] = L;
    }
}

// ---------------------------------------------------------------------------
// K1: u_hat GEMM via bf16 mma.sync, 3-term hi/lo split. fp16 output.
// grid (16 co-chunks, 1152 r). CTA tile M=128(b) x N=64(co) x K=64(i).
// (unchanged — being measured this round)
// ---------------------------------------------------------------------------
__global__ void __launch_bounds__(256)
k_uhat(const float* __restrict__ W) {
    __shared__ __align__(16) __nv_bfloat16 xh[NB * NI], xl[NB * NI];
    __shared__ __align__(16) __nv_bfloat16 wh[64 * NI], wl[64 * NI];
    const int cobase = blockIdx.x * 64;
    const int r = blockIdx.y;
    const int tid = threadIdx.x, wid = tid >> 5, lane = tid & 31;

    {
        const uint4* sh = (const uint4*)(g_xh + (size_t)r * 8192);
        const uint4* sl = (const uint4*)(g_xl + (size_t)r * 8192);
        uint4* dh = (uint4*)xh;
        uint4* dl = (uint4*)xl;
        for (int i = tid; i < 1024; i += 256) {
            dh[i] = sh[i];
            dl[i] = sl[i];
        }
    }
    for (int i = tid; i < 512; i += 256) {
        int row = i >> 3, c = i & 7;
        const float* p = W + ((size_t)r * NCO + cobase + row) * NI + c * 8;
        uint4 H, L;
        split8(*(const float4*)p, *(const float4*)(p + 4), H, L);
        unsigned o = row * 8 + (c ^ (row & 7));
        ((uint4*)wh)[o] = H;
        ((uint4*)wl)[o] = L;
    }
    __syncthreads();

    const int warpM = wid >> 1, warpN = wid & 1;
    const int lrow = (lane & 7) + ((lane >> 3) & 1) * 8;
    const unsigned csel = lane >> 4;
    unsigned arow[2], brow[2];
#pragma unroll
    for (int mt = 0; mt < 2; mt++) arow[mt] = (warpM * 32 + mt * 16 + lrow);
#pragma unroll
    for (int np = 0; np < 2; np++) brow[np] = (warpN * 32 + np * 16 + lrow);

    float acc[2][4][4];
#pragma unroll
    for (int mt = 0; mt < 2; mt++)
#pragma unroll
        for (int nt = 0; nt < 4; nt++)
#pragma unroll
            for (int j = 0; j < 4; j++) acc[mt][nt][j] = 0.f;

    const unsigned bxh = su32(xh), bxl = su32(xl);
    const unsigned bwh = su32(wh), bwl = su32(wl);

#pragma unroll
    for (int kk = 0; kk < 4; kk++) {
        unsigned Ah[2][4], Al[2][4], Bh[2][4], Bl[2][4];
#pragma unroll
        for (int mt = 0; mt < 2; mt++) {
            unsigned rs = arow[mt] & 7;
            unsigned off = arow[mt] * 128u + (((2u * kk + csel) ^ rs) << 4);
            ldm4(Ah[mt], bxh + off);
            ldm4(Al[mt], bxl + off);
        }
#pragma unroll
        for (int np = 0; np < 2; np++) {
            unsigned rs = brow[np] & 7;
            unsigned off = brow[np] * 128u + (((2u * kk + csel) ^ rs) << 4);
            ldm4(Bh[np], bwh + off);
            ldm4(Bl[np], bwl + off);
        }
#pragma unroll
        for (int mt = 0; mt < 2; mt++)
#pragma unroll
            for (int np = 0; np < 2; np++)
#pragma unroll
                for (int sub = 0; sub < 2; sub++) {
                    unsigned bh[2] = {Bh[np][sub], Bh[np][sub + 2]};
                    unsigned bl[2] = {Bl[np][sub], Bl[np][sub + 2]};
                    float* d = acc[mt][np * 2 + sub];
                    mma16816(d, Ah[mt], bh);
                    mma16816(d, Ah[mt], bl);
                    mma16816(d, Al[mt], bh);
                }
    }

    const int er0 = lane >> 2, ec = (lane & 3) * 2;
#pragma unroll
    for (int mt = 0; mt < 2; mt++)
#pragma unroll
        for (int nt = 0; nt < 4; nt++) {
            int b0 = warpM * 32 + mt * 16 + er0;
            int co = cobase + warpN * 32 + nt * 8 + ec;
            __half* p0 = &g_uhat[((size_t)b0 * NR + r) * NCO + co];
            __half* p1 = &g_uhat[((size_t)(b0 + 8) * NR + r) * NCO + co];
            *(__half2*)p0 = __floats2half2_rn(acc[mt][nt][0], acc[mt][nt][1]);
            *(__half2*)p1 = __floats2half2_rn(acc[mt][nt][2], acc[mt][nt][3]);
        }
}

// load 4 consecutive halfs (8B) -> float4
__device__ __forceinline__ float4 ld_h4(const __half* p) {
    uint2 v = *(const uint2*)p;
    float2 f0 = __half22float2(*(__half2*)&v.x);
    float2 f1 = __half22float2(*(__half2*)&v.y);
    return make_float4(f0.x, f0.y, f1.x, f1.y);
}

// ---------------------------------------------------------------------------
// K2a: pass-0 sum (uniform weights). grid (B, RCH); thread owns co-quad.
// ---------------------------------------------------------------------------
__global__ void __launch_bounds__(256)
k_sum0() {
    const int b = blockIdx.x, ch = blockIdx.y, t = threadIdx.x;
    const __half* up = g_uhat + ((size_t)b * NR + ch * RPC) * NCO + t * 4;
    float4 s = make_float4(0.f, 0.f, 0.f, 0.f);
#pragma unroll 8
    for (int rr = 0; rr < RPC; rr++) {
        float4 u = ld_h4(up + (size_t)rr * NCO);
        s.x += u.x; s.y += u.y; s.z += u.z; s.w += u.w;
    }
    ((float4*)g_spart)[((size_t)ch * NB + b) * (NCO / 4) + t] = s;
}

// ---------------------------------------------------------------------------
// K2b: routing pass, 4 r's per iteration: 4 loads in flight, one barrier
// pair per 4 r's, warps 0-3 run the 4 softmax rows concurrently.
// ---------------------------------------------------------------------------
__global__ void __launch_bounds__(256)
k_route() {
    const int b = blockIdx.x, ch = blockIdx.y, t = threadIdx.x;
    __shared__ float sm_a[4 * NC], sm_w[4 * NC];
    const __half* up = g_uhat + ((size_t)b * NR + ch * RPC) * NCO + t * 4;
    float4 vv = ((const float4*)g_vacc)[b * (NCO / 4) + t];
    float4 acc = make_float4(0.f, 0.f, 0.f, 0.f);
    float4 u[4];
#pragma unroll
    for (int j = 0; j < 4; j++) u[j] = ld_h4(up + (size_t)j * NCO);

    for (int rr = 0; rr < RPC; rr += 4) {
        float4 a[4];
#pragma unroll
        for (int j = 0; j < 4; j++) a[j] = u[j];
        if (rr + 4 < RPC) {
#pragma unroll
            for (int j = 0; j < 4; j++)
                u[j] = ld_h4(up + (size_t)(rr + 4 + j) * NCO);
        }
        float p[4];
#pragma unroll
        for (int j = 0; j < 4; j++)
            p[j] = a[j].x * vv.x + a[j].y * vv.y + a[j].z * vv.z + a[j].w * vv.w;
#pragma unroll
        for (int s = 4; s; s >>= 1)
#pragma unroll
            for (int j = 0; j < 4; j++)
                p[j] += __shfl_xor_sync(0xffffffffu, p[j], s);
        if ((t & 7) == 0) {
#pragma unroll
            for (int j = 0; j < 4; j++) sm_a[j * NC + (t >> 3)] = p[j];
        }
        __syncthreads();
        if (t < 128) {  // warp w handles softmax row w
            const int row = t >> 5, lane = t & 31;
            float av = sm_a[row * NC + lane], mx = av;
#pragma unroll
            for (int s = 16; s; s >>= 1) mx = fmaxf(mx, __shfl_xor_sync(0xffffffffu, mx, s));
            float e = __expf(av - mx), sum = e;
#pragma unroll
            for (int s = 16; s; s >>= 1) sum += __shfl_xor_sync(0xffffffffu, sum, s);
            sm_w[row * NC + lane] = e / sum;
        }
        __syncthreads();
#pragma unroll
        for (int j = 0; j < 4; j++) {
            float wj = sm_w[j * NC + (t >> 3)];
            acc.x = fmaf(wj, a[j].x, acc.x);
            acc.y = fmaf(wj, a[j].y, acc.y);
            acc.z = fmaf(wj, a[j].z, acc.z);
            acc.w = fmaf(wj, a[j].w, acc.w);
        }
    }
    ((float4*)g_spart)[((size_t)ch * NB + b) * (NCO / 4) + t] = acc;
}

// ---------------------------------------------------------------------------
// K3: reduce over chunks, squash, update Vacc / write out.
// ---------------------------------------------------------------------------
__global__ void __launch_bounds__(256)
k_squash(float* __restrict__ out, int iter, float scl) {
    const int b = blockIdx.x, t = threadIdx.x;
    float4 s = make_float4(0.f, 0.f, 0.f, 0.f);
    const float4* sp = (const float4*)g_spart + (size_t)b * (NCO / 4) + t;
#pragma unroll 4
    for (int ch = 0; ch < RCH; ch++) {
        float4 p = sp[(size_t)ch * NB * (NCO / 4)];
        s.x += p.x; s.y += p.y; s.z += p.z; s.w += p.w;
    }
    s.x *= scl; s.y *= scl; s.z *= scl; s.w *= scl;
    float ss = s.x * s.x + s.y * s.y + s.z * s.z + s.w * s.w;
    ss += __shfl_xor_sync(0xffffffffu, ss, 1);
    ss += __shfl_xor_sync(0xffffffffu, ss, 2);
    ss += __shfl_xor_sync(0xffffffffu, ss, 4);
    float norm = sqrtf(ss);
    float scale = ss / (1.0f + ss) / (norm + 1e-8f);
    float4 v = make_float4(s.x * scale, s.y * scale, s.z * scale, s.w * scale);
    float4* va = (float4*)g_vacc + b * (NCO / 4) + t;
    if (iter == 2) ((float4*)out)[b * (NCO / 4) + t] = v;
    else if (iter == 0) *va = v;
    else { float4 a = *va; a.x += v.x; a.y += v.y; a.z += v.z; a.w += v.w; *va = a; }
}

extern "C" void kernel_launch(void* const* d_in, const int* in_sizes, int n_in,
                              void* d_out, int out_size) {
    const float* x = (const float*)d_in[0];  // [B,R,I]
    const float* W = (const float*)d_in[1];  // [R,C,O,I]
    float* out = (float*)d_out;              // [B,C,O]
    // 5 xconv slices -> k_uhat is the 6th launch (the one ncu samples)
    k_xconv<<<231, 256>>>(x, 0);
    k_xconv<<<231, 256>>>(x, 231);
    k_xconv<<<231, 256>>>(x, 462);
    k_xconv<<<231, 256>>>(x, 693);
    k_xconv<<<228, 256>>>(x, 924);
    k_uhat<<<dim3(16, NR), 256>>>(W);
    k_sum0<<<dim3(NB, RCH), 256>>>();
    k_squash<<<NB, 256>>>(out, 0, 1.0f / 32.0f);
    k_route<<<dim3(NB, RCH), 256>>>();
    k_squash<<<NB, 256>>>(out, 1, 1.0f);
    k_route<<<dim3(NB, RCH), 256>>>();
    k_squash<<<NB, 256>>>(out, 2, 1.0f);
}